// round 3
// baseline (speedup 1.0000x reference)
#include <cuda_runtime.h>
#include <cstdint>

#define IN_COLS      8192
#define N_ROWS       8192
#define MAX_SLICES   1024
#define MAX_OUT_COLS 16384
#define ROWS_PER_BLK 8
#define GTHREADS     256

// out-col -> in-col map; 16B-aligned for int4 loads.
__device__ __align__(16) int g_col_idx[MAX_OUT_COLS];

// One block: decode slices (int32/int64 sniff), scan lengths, parallel
// binary-search fill of the full index map.
__global__ void __launch_bounds__(MAX_SLICES)
build_col_idx_kernel(const int* __restrict__ slices_raw, int n_slices, int out_cols) {
    __shared__ int s_scan[MAX_SLICES];
    __shared__ int s_start[MAX_SLICES];
    __shared__ int s_is64;
    int t = threadIdx.x;

    if (t == 0) {
        // int64 LE: odd 32-bit words are zero high-halves; int32: odd words are ends >= 1.
        int z = 0;
        for (int k = 0; k < 4 && k < n_slices; k++)
            z |= slices_raw[4 * k + 1] | slices_raw[4 * k + 3];
        s_is64 = (z == 0) ? 1 : 0;
    }
    __syncthreads();
    int is64 = s_is64;

    int st = 0, len = 0;
    if (t < n_slices) {
        if (is64) { st = slices_raw[4 * t]; len = slices_raw[4 * t + 2] - st; }
        else      { st = slices_raw[2 * t]; len = slices_raw[2 * t + 1] - st; }
    }
    s_start[t] = st;
    s_scan[t]  = len;
    __syncthreads();

    // Hillis-Steele inclusive scan.
    #pragma unroll
    for (int d = 1; d < MAX_SLICES; d <<= 1) {
        int v = (t >= d) ? s_scan[t - d] : 0;
        __syncthreads();
        s_scan[t] += v;
        __syncthreads();
    }

    // Parallel fill: for each output position, binary-search its slice.
    for (int pos = t; pos < out_cols; pos += MAX_SLICES) {
        int lo = 0, hi = n_slices - 1;
        while (lo < hi) {                       // first i with s_scan[i] > pos
            int mid = (lo + hi) >> 1;
            if (s_scan[mid] > pos) hi = mid; else lo = mid + 1;
        }
        int base = (lo == 0) ? 0 : s_scan[lo - 1];
        g_col_idx[pos] = s_start[lo] + (pos - base);
    }
}

// Vector gather: each thread handles 4 consecutive output cols x 8 rows.
// 4 scalar gather loads per row, one streaming float4 store.
__global__ void __launch_bounds__(GTHREADS)
gather4_kernel(const float* __restrict__ in, float* __restrict__ out, int out_cols) {
    int q  = blockIdx.x * GTHREADS + threadIdx.x;
    int p4 = q << 2;
    if (p4 >= out_cols) return;

    int4 idx = *(const int4*)&g_col_idx[p4];
    int r0 = blockIdx.y * ROWS_PER_BLK;

    const float* src = in + (size_t)r0 * IN_COLS;
    float*       dst = out + (size_t)r0 * out_cols + p4;

    #pragma unroll
    for (int j = 0; j < ROWS_PER_BLK; j++) {
        const float* s = src + (size_t)j * IN_COLS;
        float4 v;
        v.x = __ldg(s + idx.x);
        v.y = __ldg(s + idx.y);
        v.z = __ldg(s + idx.z);
        v.w = __ldg(s + idx.w);
        // streaming store: evict-first, keep input resident in L2
        asm volatile("st.global.cs.v4.f32 [%0], {%1,%2,%3,%4};"
                     :: "l"(dst + (size_t)j * out_cols),
                        "f"(v.x), "f"(v.y), "f"(v.z), "f"(v.w) : "memory");
    }
}

// Scalar fallback (out_cols not divisible by 4).
__global__ void __launch_bounds__(GTHREADS)
gather1_kernel(const float* __restrict__ in, float* __restrict__ out, int out_cols) {
    int p = blockIdx.x * GTHREADS + threadIdx.x;
    if (p >= out_cols) return;
    int idx = g_col_idx[p];
    int r0  = blockIdx.y * ROWS_PER_BLK;
    const float* src = in + (size_t)r0 * IN_COLS + idx;
    float*       dst = out + (size_t)r0 * out_cols + p;
    #pragma unroll
    for (int j = 0; j < ROWS_PER_BLK; j++)
        dst[(size_t)j * out_cols] = __ldg(src + (size_t)j * IN_COLS);
}

extern "C" void kernel_launch(void* const* d_in, const int* in_sizes, int n_in,
                              void* d_out, int out_size) {
    const float* input      = (const float*)d_in[0];
    const int*   slices_raw = (const int*)d_in[1];
    float*       out        = (float*)d_out;

    int n_slices = in_sizes[1] / 2;      // 600
    int out_cols = out_size / N_ROWS;    // 12500

    build_col_idx_kernel<<<1, MAX_SLICES>>>(slices_raw, n_slices, out_cols);

    if ((out_cols & 3) == 0) {
        int quads = out_cols >> 2;
        dim3 grid((quads + GTHREADS - 1) / GTHREADS, N_ROWS / ROWS_PER_BLK);
        gather4_kernel<<<grid, GTHREADS>>>(input, out, out_cols);
    } else {
        dim3 grid((out_cols + GTHREADS - 1) / GTHREADS, N_ROWS / ROWS_PER_BLK);
        gather1_kernel<<<grid, GTHREADS>>>(input, out, out_cols);
    }
}

// round 4
// speedup vs baseline: 1.0879x; 1.0879x over previous
#include <cuda_runtime.h>
#include <cstdint>

#define IN_COLS      8192
#define N_ROWS       8192
#define MAX_SLICES   1024
#define MAX_OUT_COLS 16384
#define ROWS_PER_BLK 16
#define GTHREADS     256

// out-col -> in-col map.
__device__ __align__(16) int g_col_idx[MAX_OUT_COLS];

// One block: decode slices (int32/int64 sniff), scan lengths, parallel
// binary-search fill of the full index map.
__global__ void __launch_bounds__(MAX_SLICES)
build_col_idx_kernel(const int* __restrict__ slices_raw, int n_slices, int out_cols) {
    __shared__ int s_scan[MAX_SLICES];
    __shared__ int s_start[MAX_SLICES];
    __shared__ int s_is64;
    int t = threadIdx.x;

    if (t == 0) {
        // int64 LE: odd 32-bit words are zero high-halves; int32: odd words are ends >= 1.
        int z = 0;
        for (int k = 0; k < 4 && k < n_slices; k++)
            z |= slices_raw[4 * k + 1] | slices_raw[4 * k + 3];
        s_is64 = (z == 0) ? 1 : 0;
    }
    __syncthreads();
    int is64 = s_is64;

    int st = 0, len = 0;
    if (t < n_slices) {
        if (is64) { st = slices_raw[4 * t]; len = slices_raw[4 * t + 2] - st; }
        else      { st = slices_raw[2 * t]; len = slices_raw[2 * t + 1] - st; }
    }
    s_start[t] = st;
    s_scan[t]  = len;
    __syncthreads();

    // Hillis-Steele inclusive scan.
    #pragma unroll
    for (int d = 1; d < MAX_SLICES; d <<= 1) {
        int v = (t >= d) ? s_scan[t - d] : 0;
        __syncthreads();
        s_scan[t] += v;
        __syncthreads();
    }

    // Parallel fill: binary-search the owning slice for each output position.
    for (int pos = t; pos < out_cols; pos += MAX_SLICES) {
        int lo = 0, hi = n_slices - 1;
        while (lo < hi) {                       // first i with s_scan[i] > pos
            int mid = (lo + hi) >> 1;
            if (s_scan[mid] > pos) hi = mid; else lo = mid + 1;
        }
        int base = (lo == 0) ? 0 : s_scan[lo - 1];
        g_col_idx[pos] = s_start[lo] + (pos - base);
    }
}

// Scalar gather: one output column per thread (warp-contiguous index stream),
// 16 rows per thread for deep load MLP.
__global__ void __launch_bounds__(GTHREADS)
gather_kernel(const float* __restrict__ in, float* __restrict__ out, int out_cols) {
    int p = blockIdx.x * GTHREADS + threadIdx.x;
    if (p >= out_cols) return;

    int idx = g_col_idx[p];
    int r0  = blockIdx.y * ROWS_PER_BLK;

    const float* src = in  + (size_t)r0 * IN_COLS  + idx;
    float*       dst = out + (size_t)r0 * out_cols + p;

    #pragma unroll
    for (int j = 0; j < ROWS_PER_BLK; j++)
        dst[(size_t)j * out_cols] = __ldg(src + (size_t)j * IN_COLS);
}

// Tail-safe generic row loop (used only if N_ROWS % ROWS_PER_BLK != 0 — not here).
extern "C" void kernel_launch(void* const* d_in, const int* in_sizes, int n_in,
                              void* d_out, int out_size) {
    const float* input      = (const float*)d_in[0];
    const int*   slices_raw = (const int*)d_in[1];
    float*       out        = (float*)d_out;

    int n_slices = in_sizes[1] / 2;      // 600
    int out_cols = out_size / N_ROWS;    // 12500

    build_col_idx_kernel<<<1, MAX_SLICES>>>(slices_raw, n_slices, out_cols);

    dim3 grid((out_cols + GTHREADS - 1) / GTHREADS, N_ROWS / ROWS_PER_BLK);
    gather_kernel<<<grid, GTHREADS>>>(input, out, out_cols);
}